// round 3
// baseline (speedup 1.0000x reference)
#include <cuda_runtime.h>
#include <cuda_bf16.h>

// out[i,j] = log1p(max(0, Gauss9 ⊛ T)) ,  T[i,j] = Resize2x(img)[N-1-j, i] + 0.01*noise[i,j]
// Resize2x: half-pixel-center bilinear (jax.image.resize 'linear'), weights {0.25,0.75}, edge clamp.
// Blur: separable 9-tap sigma=1 Gaussian, 'symmetric' padding on T.

#define NN 4096
#define MM 2048
#define TI 64
#define TJ 64
#define HALO 4
#define LI (TI + 2*HALO)   // 72
#define LJ (TJ + 2*HALO)   // 72
#define P1 73              // s1 pitch (odd -> conflict-free column writes)
#define P2 76              // s2 pitch (mult of 4 -> float4 loads)

__device__ __forceinline__ int symidx(int p) {
    // numpy 'symmetric' pad: -1 -> 0, -2 -> 1, N -> N-1, ...
    p = (p < 0) ? (-1 - p) : p;
    return (p >= NN) ? (2 * NN - 1 - p) : p;
}

__global__ __launch_bounds__(256)
void fused_aug_kernel(const float* __restrict__ img,
                      const float* __restrict__ noise,
                      float* __restrict__ out)
{
    __shared__ float s1[LI * P1];                       // T tile + halo
    __shared__ __align__(16) float s2[TI * P2];         // vertically blurred

    // 9-tap sigma=1 Gaussian, normalized by discrete sum (matches reference)
    const float KW[9] = {1.3383062e-4f, 4.4318616e-3f, 5.3991124e-2f,
                         2.4197145e-1f, 3.9894347e-1f, 2.4197145e-1f,
                         5.3991124e-2f, 4.4318616e-3f, 1.3383062e-4f};

    const int t  = threadIdx.x;
    const int i0 = (int)blockIdx.y * TI - HALO;
    const int j0 = (int)blockIdx.x * TJ - HALO;

    // ---- Phase 1: noise contribution (coalesced along j) -> s1 ----
    #pragma unroll 5
    for (int idx = t; idx < LI * LJ; idx += 256) {
        int ii = idx / LJ;
        int jj = idx - ii * LJ;
        int gi = symidx(i0 + ii);
        int gj = symidx(j0 + jj);
        s1[ii * P1 + jj] = 0.01f * __ldg(&noise[gi * NN + gj]);
    }
    __syncthreads();

    // ---- Phase 2: rotated resized image (coalesced along i) accumulated into s1 ----
    #pragma unroll 5
    for (int idx = t; idx < LI * LJ; idx += 256) {
        int jj = idx / LI;
        int ii = idx - jj * LI;
        int b  = symidx(i0 + ii);            // resize column coord = i
        int a  = NN - 1 - symidx(j0 + jj);   // resize row coord = N-1-j
        float cy = 0.5f * (float)a - 0.25f;  // half-pixel centers, scale 2x
        float cx = 0.5f * (float)b - 0.25f;
        float y0f = floorf(cy);
        float x0f = floorf(cx);
        float fy = cy - y0f;
        float fx = cx - x0f;
        int y0 = max((int)y0f, 0);
        int y1 = min((int)y0f + 1, MM - 1);
        int x0 = max((int)x0f, 0);
        int x1 = min((int)x0f + 1, MM - 1);
        const float* r0 = img + (size_t)y0 * MM;
        const float* r1 = img + (size_t)y1 * MM;
        float a00 = __ldg(&r0[x0]);
        float a01 = __ldg(&r0[x1]);
        float a10 = __ldg(&r1[x0]);
        float a11 = __ldg(&r1[x1]);
        float v0 = fmaf(fx, a01 - a00, a00);
        float v1 = fmaf(fx, a11 - a10, a10);
        s1[ii * P1 + jj] += fmaf(fy, v1 - v0, v0);
    }
    __syncthreads();

    // ---- Phase 3: vertical 9-tap blur; 4 rows per task via register window ----
    for (int idx = t; idx < (TI / 4) * LJ; idx += 256) {
        int ib = idx / LJ;                   // 0..15
        int jj = idx - ib * LJ;
        int ii = ib * 4;
        float v[12];
        #pragma unroll
        for (int r = 0; r < 12; r++) v[r] = s1[(ii + r) * P1 + jj];
        #pragma unroll
        for (int r = 0; r < 4; r++) {
            float acc = 0.0f;
            #pragma unroll
            for (int d = 0; d < 9; d++) acc = fmaf(KW[d], v[r + d], acc);
            s2[(ii + r) * P2 + jj] = acc;
        }
    }
    __syncthreads();

    // ---- Phase 4: horizontal blur + clip + log1p; 4 outputs/thread, float4 store ----
    const int oi0 = (int)blockIdx.y * TI;
    const int oj0 = (int)blockIdx.x * TJ;
    #pragma unroll
    for (int k = 0; k < (TI * (TJ / 4)) / 256; k++) {
        int idx = t + k * 256;
        int ii = idx >> 4;                   // / (TJ/4)
        int jb = idx & 15;
        int jj = jb * 4;
        const float* row = &s2[ii * P2 + jj];
        float4 a0 = *(const float4*)(row);
        float4 a1 = *(const float4*)(row + 4);
        float4 a2 = *(const float4*)(row + 8);
        float v[12] = {a0.x, a0.y, a0.z, a0.w,
                       a1.x, a1.y, a1.z, a1.w,
                       a2.x, a2.y, a2.z, a2.w};
        float4 o;
        float* op = (float*)&o;
        #pragma unroll
        for (int r = 0; r < 4; r++) {
            float acc = 0.0f;
            #pragma unroll
            for (int d = 0; d < 9; d++) acc = fmaf(KW[d], v[r + d], acc);
            acc = fmaxf(acc, 0.0f);
            op[r] = log1pf(acc);
        }
        *(float4*)&out[(size_t)(oi0 + ii) * NN + (oj0 + jj)] = o;
    }
}

extern "C" void kernel_launch(void* const* d_in, const int* in_sizes, int n_in,
                              void* d_out, int out_size) {
    const float* img   = (const float*)d_in[0];   // (1,2048,2048) f32
    const float* noise = (const float*)d_in[1];   // (1,4096,4096) f32
    if (n_in >= 2 && in_sizes[0] > in_sizes[1]) { // defensive: order by size
        const float* tmp = img; img = noise; noise = tmp;
    }
    dim3 grid(NN / TJ, NN / TI);   // 64 x 64 tiles
    fused_aug_kernel<<<grid, 256>>>(img, noise, (float*)d_out);
}